// round 2
// baseline (speedup 1.0000x reference)
#include <cuda_runtime.h>
#include <math.h>

// Problem constants (fixed by dataset)
#define NN     30000
#define NEDGE  960000
#define ETOT   990000      // + self loops
#define INDIM  4527
#define HOGSPL 4464
#define HID    128
#define NG     64

// ---------------- scratch (static device memory; no allocation) ----------------
// layout offsets (floats)
static constexpr size_t OFF_ATTN = 0;                         // 30000*2
static constexpr size_t OFF_H1   = OFF_ATTN + 2UL*NN;         // 30000*256
static constexpr size_t OFF_AS1  = OFF_H1   + 256UL*NN;       // 30000*2
static constexpr size_t OFF_AD1  = OFF_AS1  + 2UL*NN;
static constexpr size_t OFF_E1   = OFF_AD1  + 2UL*NN;         // 990000*2
static constexpr size_t OFF_M1   = OFF_E1   + 2UL*ETOT;       // 30000*2
static constexpr size_t OFF_DEN1 = OFF_M1   + 2UL*NN;
static constexpr size_t OFF_OUT1 = OFF_DEN1 + 2UL*NN;         // 30000*256
static constexpr size_t OFF_X2   = OFF_OUT1 + 256UL*NN;       // 30000*256
static constexpr size_t OFF_H2   = OFF_X2   + 256UL*NN;       // 30000*128
static constexpr size_t OFF_AS2  = OFF_H2   + 128UL*NN;       // 30000
static constexpr size_t OFF_AD2  = OFF_AS2  + 1UL*NN;
static constexpr size_t OFF_E2   = OFF_AD2  + 1UL*NN;         // 990000
static constexpr size_t OFF_M2   = OFF_E2   + 1UL*ETOT;       // 30000
static constexpr size_t OFF_DEN2 = OFF_M2   + 1UL*NN;
static constexpr size_t OFF_OUT2 = OFF_DEN2 + 1UL*NN;         // 30000*128
static constexpr size_t OFF_POOL = OFF_OUT2 + 128UL*NN;       // 64*128
static constexpr size_t OFF_CNT  = OFF_POOL + 128UL*NG;       // 64
static constexpr size_t TOTAL_F  = OFF_CNT  + NG;

__device__ float g_buf[TOTAL_F];

// ---------------- helpers ----------------
__device__ __forceinline__ void atomicMaxF(float* addr, float v) {
    if (v >= 0.0f) atomicMax((int*)addr, __float_as_int(v));
    else           atomicMin((unsigned int*)addr, __float_as_uint(v));
}

__device__ __forceinline__ void red_add_v4(float* p, float4 v) {
    asm volatile("red.global.add.v4.f32 [%0], {%1,%2,%3,%4};"
                 :: "l"(p), "f"(v.x), "f"(v.y), "f"(v.z), "f"(v.w) : "memory");
}

// ---------------- init (zero / -inf the accumulators each launch) ----------------
__global__ void init_kernel(float* out1, float* out2, float* m1, float* den1,
                            float* m2, float* den2, float* pool, float* cnt) {
    size_t i = (size_t)blockIdx.x * blockDim.x + threadIdx.x;   // exactly 7,680,000 threads
    out1[i] = 0.0f;
    if (i < 128UL*NN) out2[i] = 0.0f;
    if (i < 2UL*NN)  { m1[i] = -INFINITY; den1[i] = 0.0f; }
    if (i < 1UL*NN)  { m2[i] = -INFINITY; den2[i] = 0.0f; }
    if (i < 128UL*NG) pool[i] = 0.0f;
    if (i < NG)       cnt[i] = 0.0f;
}

// ---------------- attn = softmax(x @ attn_W + attn_b) ----------------
__global__ void attn_kernel(const float* __restrict__ x, const float* __restrict__ aW,
                            const float* __restrict__ ab, float* __restrict__ attn,
                            int n, int K) {
    int warp = (blockIdx.x * blockDim.x + threadIdx.x) >> 5;
    int lane = threadIdx.x & 31;
    if (warp >= n) return;
    const float* row = x + (size_t)warp * K;
    float l0 = 0.f, l1 = 0.f;
    for (int k = lane; k < K; k += 32) {
        float v = row[k];
        l0 += v * aW[2*k];
        l1 += v * aW[2*k+1];
    }
    #pragma unroll
    for (int o = 16; o; o >>= 1) {
        l0 += __shfl_down_sync(0xffffffffu, l0, o);
        l1 += __shfl_down_sync(0xffffffffu, l1, o);
    }
    if (lane == 0) {
        l0 += ab[0]; l1 += ab[1];
        float m  = fmaxf(l0, l1);
        float e0 = __expf(l0 - m), e1 = __expf(l1 - m);
        float s  = e0 + e1;
        attn[2*warp]   = e0 / s;
        attn[2*warp+1] = e1 / s;
    }
}

// ---------------- tiled fp32 GEMM:  C[M,N] = rowscale(A[M,K]) @ B[K,N] ----------------
// rowscale (optional): A[m,k] *= (k < split ? rs[2m] : rs[2m+1])
// NOTE: A row stride K may be odd (4527) -> A loaded with scalar LDG only.
__global__ __launch_bounds__(256, 2)
void gemm_kernel(const float* __restrict__ A, const float* __restrict__ B,
                 float* __restrict__ C, int M, int N, int K,
                 const float* __restrict__ rowscale, int split) {
    __shared__ float As[16][132];   // padded: transposed scalar stores ~2-way conflict
    __shared__ float Bs[16][132];   // row stride mult of 4 -> float4-aligned rows
    int tid  = threadIdx.x;
    int m0   = blockIdx.x * 128;
    int n0   = blockIdx.y * 128;
    int trow = tid >> 4;         // 0..15 (M direction)
    int tcol = tid & 15;         // 0..15 (N direction)

    float acc[8][8];
    #pragma unroll
    for (int i = 0; i < 8; i++)
        #pragma unroll
        for (int j = 0; j < 8; j++) acc[i][j] = 0.f;

    // A-load thread mapping: half-warp (16 lanes) per row, 16 consecutive k
    int arow = tid >> 4;   // 0..15
    int ak   = tid & 15;   // 0..15

    int ntiles = (K + 15) >> 4;
    for (int t = 0; t < ntiles; t++) {
        int k0 = t << 4;
        // load A tile (128 rows x 16 k), scalar coalesced, 8 passes
        #pragma unroll
        for (int pass = 0; pass < 8; pass++) {
            int row = arow + pass * 16;
            int m   = m0 + row;
            int kg  = k0 + ak;
            float v = 0.f;
            if (m < M && kg < K) {
                v = A[(size_t)m * K + kg];
                if (rowscale)
                    v *= (kg < split) ? rowscale[2*m] : rowscale[2*m+1];
            }
            As[ak][row] = v;
        }
        // load B tile (16 k x 128 n), float4 (B row stride is mult of 4)
        #pragma unroll
        for (int l = 0; l < 2; l++) {
            int idx = tid + l * 256;
            int row = idx >> 5;
            int c4  = (idx & 31) << 2;
            int kg  = k0 + row;
            float4 v = make_float4(0.f, 0.f, 0.f, 0.f);
            if (kg < K) v = *(const float4*)(B + (size_t)kg * N + n0 + c4);
            *(float4*)&Bs[row][c4] = v;
        }
        __syncthreads();
        #pragma unroll
        for (int kk = 0; kk < 16; kk++) {
            float ar[8], br[8];
            *(float4*)&ar[0] = *(float4*)&As[kk][trow*8];
            *(float4*)&ar[4] = *(float4*)&As[kk][trow*8+4];
            *(float4*)&br[0] = *(float4*)&Bs[kk][tcol*8];
            *(float4*)&br[4] = *(float4*)&Bs[kk][tcol*8+4];
            #pragma unroll
            for (int i = 0; i < 8; i++)
                #pragma unroll
                for (int j = 0; j < 8; j++) acc[i][j] += ar[i] * br[j];
        }
        __syncthreads();
    }
    #pragma unroll
    for (int i = 0; i < 8; i++) {
        int m = m0 + trow*8 + i;
        if (m < M) {
            float* cp = C + (size_t)m * N + n0 + tcol*8;
            *(float4*)cp       = make_float4(acc[i][0], acc[i][1], acc[i][2], acc[i][3]);
            *(float4*)(cp + 4) = make_float4(acc[i][4], acc[i][5], acc[i][6], acc[i][7]);
        }
    }
}

// ---------------- per-node attention scalars: as[n,h] = h[n,h,:]·a_src[h,:] ----------------
__global__ void alpha_kernel(const float* __restrict__ h, const float* __restrict__ asrc,
                             const float* __restrict__ adst, float* __restrict__ oas,
                             float* __restrict__ oad, int n, int heads) {
    int warp = (blockIdx.x * blockDim.x + threadIdx.x) >> 5;
    int lane = threadIdx.x & 31;
    if (warp >= n) return;
    const float* hr = h + (size_t)warp * heads * HID;
    for (int hh = 0; hh < heads; hh++) {
        float s = 0.f, d = 0.f;
        #pragma unroll
        for (int k = lane; k < HID; k += 32) {
            float v = hr[hh*HID + k];
            s += v * asrc[hh*HID + k];
            d += v * adst[hh*HID + k];
        }
        #pragma unroll
        for (int o = 16; o; o >>= 1) {
            s += __shfl_down_sync(0xffffffffu, s, o);
            d += __shfl_down_sync(0xffffffffu, d, o);
        }
        if (lane == 0) { oas[warp*heads + hh] = s; oad[warp*heads + hh] = d; }
    }
}

// ---------------- edge pass A: e = leaky(as[src]+ad[dst]); segment max over dst ----------------
__global__ void edge_max_kernel(const int* __restrict__ ei, int ne, int etot,
                                const float* __restrict__ as, const float* __restrict__ ad,
                                float* __restrict__ estore, float* __restrict__ mbuf, int heads) {
    int i = blockIdx.x * blockDim.x + threadIdx.x;
    if (i >= etot * heads) return;
    int e = i / heads, h = i - e * heads;
    int s, d;
    if (e < ne) { s = ei[e]; d = ei[ne + e]; } else { s = d = e - ne; }
    float v = as[s*heads + h] + ad[d*heads + h];
    v = v > 0.f ? v : 0.2f * v;
    estore[i] = v;
    atomicMaxF(&mbuf[d*heads + h], v);
}

// ---------------- edge pass B: e' = exp(e - m[dst]); segment sum over dst ----------------
__global__ void edge_exp_kernel(const int* __restrict__ ei, int ne, int etot,
                                float* __restrict__ estore, const float* __restrict__ mbuf,
                                float* __restrict__ den, int heads) {
    int i = blockIdx.x * blockDim.x + threadIdx.x;
    if (i >= etot * heads) return;
    int e = i / heads, h = i - e * heads;
    int d;
    if (e < ne) { d = ei[ne + e]; } else { d = e - ne; }
    float ex = __expf(estore[i] - mbuf[d*heads + h]);
    estore[i] = ex;
    atomicAdd(&den[d*heads + h], ex);
}

// ---------------- edge pass C: out[dst] += alpha * h[src]  (warp per edge, v4 RED) ------------
__global__ void edge_scatter_kernel(const int* __restrict__ ei, int ne, int etot,
                                    const float* __restrict__ estore, const float* __restrict__ den,
                                    const float* __restrict__ h, float* __restrict__ out, int heads) {
    int warp = (blockIdx.x * blockDim.x + threadIdx.x) >> 5;
    int lane = threadIdx.x & 31;
    if (warp >= etot) return;
    int s, d;
    if (warp < ne) { s = ei[warp]; d = ei[ne + warp]; } else { s = d = warp - ne; }
    int D = heads * HID;
    const float* hr = h + (size_t)s * D;
    float* orow = out + (size_t)d * D;
    for (int hh = 0; hh < heads; hh++) {
        float a = estore[warp*heads + hh] / (den[d*heads + hh] + 1e-16f);
        int base = hh*HID + lane*4;
        float4 v = *(const float4*)(hr + base);
        v.x *= a; v.y *= a; v.z *= a; v.w *= a;
        red_add_v4(orow + base, v);
    }
}

// ---------------- elementwise bias + relu ----------------
__global__ void bias_relu_kernel(const float* __restrict__ in, const float* __restrict__ b,
                                 float* __restrict__ out, size_t total, int Dmask) {
    size_t i = (size_t)blockIdx.x * blockDim.x + threadIdx.x;
    if (i >= total) return;
    out[i] = fmaxf(in[i] + b[i & Dmask], 0.f);
}

// ---------------- pooling: mean over batch segments (warp per node) ----------------
__global__ void pool_kernel(const float* __restrict__ out2, const float* __restrict__ b2,
                            const int* __restrict__ batch, float* __restrict__ sums,
                            float* __restrict__ cnt, int n) {
    int warp = (blockIdx.x * blockDim.x + threadIdx.x) >> 5;
    int lane = threadIdx.x & 31;
    if (warp >= n) return;
    int b = batch[warp];
    int base = lane * 4;
    float4 v  = *(const float4*)(out2 + (size_t)warp * HID + base);
    float4 bb = *(const float4*)(b2 + base);
    v.x = fmaxf(v.x + bb.x, 0.f);
    v.y = fmaxf(v.y + bb.y, 0.f);
    v.z = fmaxf(v.z + bb.z, 0.f);
    v.w = fmaxf(v.w + bb.w, 0.f);
    red_add_v4(sums + (size_t)b * HID + base, v);
    if (lane == 0) atomicAdd(&cnt[b], 1.0f);
}

// ---------------- classifier: relu(pooled@Wc1+bc1)@Wc2+bc2 ----------------
__global__ void classifier_kernel(const float* __restrict__ sums, const float* __restrict__ cnt,
                                  const float* __restrict__ Wc1, const float* __restrict__ bc1,
                                  const float* __restrict__ Wc2, const float* __restrict__ bc2,
                                  float* __restrict__ out) {
    int g = blockIdx.x;
    int t = threadIdx.x;        // 64 threads
    __shared__ float p[128], z[64];
    float c = fmaxf(cnt[g], 1.0f);
    p[t]      = sums[g*128 + t] / c;
    p[t + 64] = sums[g*128 + 64 + t] / c;
    __syncthreads();
    float acc = bc1[t];
    #pragma unroll 8
    for (int k = 0; k < 128; k++) acc += p[k] * Wc1[k*64 + t];
    z[t] = fmaxf(acc, 0.f);
    __syncthreads();
    if (t < 4) {
        float a = bc2[t];
        #pragma unroll 8
        for (int j = 0; j < 64; j++) a += z[j] * Wc2[j*4 + t];
        out[g*4 + t] = a;
    }
}

// ---------------- launch ----------------
extern "C" void kernel_launch(void* const* d_in, const int* in_sizes, int n_in,
                              void* d_out, int out_size) {
    const float* x       = (const float*)d_in[0];
    const int*   ei      = (const int*)  d_in[1];
    const int*   batch   = (const int*)  d_in[2];
    const float* attn_W  = (const float*)d_in[3];
    const float* attn_b  = (const float*)d_in[4];
    const float* W1      = (const float*)d_in[5];
    const float* a_src1  = (const float*)d_in[6];
    const float* a_dst1  = (const float*)d_in[7];
    const float* b1      = (const float*)d_in[8];
    const float* W2      = (const float*)d_in[9];
    const float* a_src2  = (const float*)d_in[10];
    const float* a_dst2  = (const float*)d_in[11];
    const float* b2      = (const float*)d_in[12];
    const float* Wc1     = (const float*)d_in[13];
    const float* bc1     = (const float*)d_in[14];
    const float* Wc2     = (const float*)d_in[15];
    const float* bc2     = (const float*)d_in[16];
    float* out = (float*)d_out;

    int n    = in_sizes[2];          // 30000
    int ne   = in_sizes[1] / 2;      // 960000
    int etot = ne + n;               // 990000
    int K    = in_sizes[0] / n;      // 4527

    float* base;
    cudaGetSymbolAddress((void**)&base, g_buf);
    float* attn = base + OFF_ATTN;
    float* h1   = base + OFF_H1;
    float* as1  = base + OFF_AS1;
    float* ad1  = base + OFF_AD1;
    float* e1   = base + OFF_E1;
    float* m1   = base + OFF_M1;
    float* den1 = base + OFF_DEN1;
    float* out1 = base + OFF_OUT1;
    float* x2   = base + OFF_X2;
    float* h2   = base + OFF_H2;
    float* as2  = base + OFF_AS2;
    float* ad2  = base + OFF_AD2;
    float* e2   = base + OFF_E2;
    float* m2   = base + OFF_M2;
    float* den2 = base + OFF_DEN2;
    float* out2 = base + OFF_OUT2;
    float* pool = base + OFF_POOL;
    float* cnt  = base + OFF_CNT;

    // 0) init accumulators
    init_kernel<<<(n * 256) / 256, 256>>>(out1, out2, m1, den1, m2, den2, pool, cnt);

    // 1) attention gate softmax
    attn_kernel<<<(n + 7) / 8, 256>>>(x, attn_W, attn_b, attn, n, K);

    // 2) GEMM1: h1 = fused @ W1  (row-scaled A, split at HOG boundary)
    {
        dim3 grid((n + 127) / 128, 2);
        gemm_kernel<<<grid, 256>>>(x, W1, h1, n, 2*HID, K, attn, HOGSPL);
    }

    // 3) layer-1 attention scalars
    alpha_kernel<<<(n + 7) / 8, 256>>>(h1, a_src1, a_dst1, as1, ad1, n, 2);

    // 4) layer-1 edge softmax + aggregation
    edge_max_kernel<<<(etot*2 + 255) / 256, 256>>>(ei, ne, etot, as1, ad1, e1, m1, 2);
    edge_exp_kernel<<<(etot*2 + 255) / 256, 256>>>(ei, ne, etot, e1, m1, den1, 2);
    edge_scatter_kernel<<<(etot + 7) / 8, 256>>>(ei, ne, etot, e1, den1, h1, out1, 2);

    // 5) x2 = relu(out1 + b1)
    bias_relu_kernel<<<(n * 256 + 255) / 256, 256>>>(out1, b1, x2, (size_t)n * 256, 255);

    // 6) GEMM2: h2 = x2 @ W2
    {
        dim3 grid((n + 127) / 128, 1);
        gemm_kernel<<<grid, 256>>>(x2, W2, h2, n, HID, 2*HID, nullptr, 0);
    }

    // 7) layer-2 attention scalars
    alpha_kernel<<<(n + 7) / 8, 256>>>(h2, a_src2, a_dst2, as2, ad2, n, 1);

    // 8) layer-2 edge softmax + aggregation
    edge_max_kernel<<<(etot + 255) / 256, 256>>>(ei, ne, etot, as2, ad2, e2, m2, 1);
    edge_exp_kernel<<<(etot + 255) / 256, 256>>>(ei, ne, etot, e2, m2, den2, 1);
    edge_scatter_kernel<<<(etot + 7) / 8, 256>>>(ei, ne, etot, e2, den2, h2, out2, 1);

    // 9) pooling: mean over graphs of relu(out2 + b2)
    pool_kernel<<<(n + 7) / 8, 256>>>(out2, b2, batch, pool, cnt, n);

    // 10) classifier head
    classifier_kernel<<<NG, 64>>>(pool, cnt, Wc1, bc1, Wc2, bc2, out);
}

// round 10
// speedup vs baseline: 1.8662x; 1.8662x over previous
#include <cuda_runtime.h>
#include <math.h>
#include <stdint.h>

// Problem constants (fixed by dataset)
#define NN     30000
#define NEDGE  960000
#define ETOT   990000      // + self loops
#define INDIM  4527
#define HOGSPL 4464
#define HID    128
#define NG     64

// ---------------- scratch (static device memory; no allocation) ----------------
static constexpr size_t OFF_ATTN = 0;                         // 30000*2
static constexpr size_t OFF_H1   = OFF_ATTN + 2UL*NN;         // 30000*256
static constexpr size_t OFF_AS1  = OFF_H1   + 256UL*NN;       // 30000*2
static constexpr size_t OFF_AD1  = OFF_AS1  + 2UL*NN;
static constexpr size_t OFF_E1   = OFF_AD1  + 2UL*NN;         // 990000*2
static constexpr size_t OFF_M1   = OFF_E1   + 2UL*ETOT;       // 30000*2
static constexpr size_t OFF_DEN1 = OFF_M1   + 2UL*NN;
static constexpr size_t OFF_OUT1 = OFF_DEN1 + 2UL*NN;         // 30000*256
static constexpr size_t OFF_X2   = OFF_OUT1 + 256UL*NN;       // 30000*256
static constexpr size_t OFF_H2   = OFF_X2   + 256UL*NN;       // 30000*128
static constexpr size_t OFF_AS2  = OFF_H2   + 128UL*NN;       // 30000
static constexpr size_t OFF_AD2  = OFF_AS2  + 1UL*NN;
static constexpr size_t OFF_E2   = OFF_AD2  + 1UL*NN;         // 990000
static constexpr size_t OFF_M2   = OFF_E2   + 1UL*ETOT;       // 30000
static constexpr size_t OFF_DEN2 = OFF_M2   + 1UL*NN;
static constexpr size_t OFF_OUT2 = OFF_DEN2 + 1UL*NN;         // 30000*128
static constexpr size_t OFF_POOL = OFF_OUT2 + 128UL*NN;       // 64*128
static constexpr size_t OFF_CNT  = OFF_POOL + 128UL*NG;       // 64
static constexpr size_t TOTAL_F  = OFF_CNT  + NG;

__device__ float g_buf[TOTAL_F];

// ---------------- helpers ----------------
__device__ __forceinline__ void atomicMaxF(float* addr, float v) {
    if (v >= 0.0f) atomicMax((int*)addr, __float_as_int(v));
    else           atomicMin((unsigned int*)addr, __float_as_uint(v));
}

__device__ __forceinline__ void red_add_v4(float* p, float4 v) {
    asm volatile("red.global.add.v4.f32 [%0], {%1,%2,%3,%4};"
                 :: "l"(p), "f"(v.x), "f"(v.y), "f"(v.z), "f"(v.w) : "memory");
}

__device__ __forceinline__ uint32_t f2tf32(float f) {
    uint32_t u;
    asm("cvt.rna.tf32.f32 %0, %1;" : "=r"(u) : "f"(f));
    return u;
}

__device__ __forceinline__ void mma_tf32(float* d, const uint32_t* a, const uint32_t* b) {
    asm volatile(
        "mma.sync.aligned.m16n8k8.row.col.f32.tf32.tf32.f32 "
        "{%0,%1,%2,%3}, {%4,%5,%6,%7}, {%8,%9}, {%0,%1,%2,%3};"
        : "+f"(d[0]), "+f"(d[1]), "+f"(d[2]), "+f"(d[3])
        : "r"(a[0]), "r"(a[1]), "r"(a[2]), "r"(a[3]), "r"(b[0]), "r"(b[1]));
}

// cp.async 4B with zero-fill when sz==0 (OOB-safe: no global read issued)
__device__ __forceinline__ void cp_async4(uint32_t smem_dst, const void* gsrc, int sz) {
    asm volatile("cp.async.ca.shared.global [%0], [%1], 4, %2;"
                 :: "r"(smem_dst), "l"(gsrc), "r"(sz));
}
__device__ __forceinline__ void cp_async16(uint32_t smem_dst, const void* gsrc, int sz) {
    asm volatile("cp.async.cg.shared.global [%0], [%1], 16, %2;"
                 :: "r"(smem_dst), "l"(gsrc), "r"(sz));
}
__device__ __forceinline__ void cp_commit() {
    asm volatile("cp.async.commit_group;");
}

// ---------------- init (zero / -inf the accumulators each launch) ----------------
__global__ void init_kernel(float* out1, float* out2, float* m1, float* den1,
                            float* m2, float* den2, float* pool, float* cnt) {
    size_t i = (size_t)blockIdx.x * blockDim.x + threadIdx.x;   // exactly 7,680,000 threads
    out1[i] = 0.0f;
    if (i < 128UL*NN) out2[i] = 0.0f;
    if (i < 2UL*NN)  { m1[i] = -INFINITY; den1[i] = 0.0f; }
    if (i < 1UL*NN)  { m2[i] = -INFINITY; den2[i] = 0.0f; }
    if (i < 128UL*NG) pool[i] = 0.0f;
    if (i < NG)       cnt[i] = 0.0f;
}

// ---------------- attn = softmax(x @ attn_W + attn_b) ----------------
__global__ void attn_kernel(const float* __restrict__ x, const float* __restrict__ aW,
                            const float* __restrict__ ab, float* __restrict__ attn,
                            int n, int K) {
    int warp = (blockIdx.x * blockDim.x + threadIdx.x) >> 5;
    int lane = threadIdx.x & 31;
    if (warp >= n) return;
    const float* row = x + (size_t)warp * K;
    float l0 = 0.f, l1 = 0.f;
    for (int k = lane; k < K; k += 32) {
        float v = row[k];
        l0 += v * aW[2*k];
        l1 += v * aW[2*k+1];
    }
    #pragma unroll
    for (int o = 16; o; o >>= 1) {
        l0 += __shfl_down_sync(0xffffffffu, l0, o);
        l1 += __shfl_down_sync(0xffffffffu, l1, o);
    }
    if (lane == 0) {
        l0 += ab[0]; l1 += ab[1];
        float m  = fmaxf(l0, l1);
        float e0 = __expf(l0 - m), e1 = __expf(l1 - m);
        float s  = e0 + e1;
        attn[2*warp]   = e0 / s;
        attn[2*warp+1] = e1 / s;
    }
}

// ---------------- tf32 tensor-core GEMM, cp.async double-buffered ----------------
// C[M,N] = rowscale(A[M,K]) @ B[K,N]
// Grid mapping: blockIdx.x = N-block, blockIdx.y = M-block -> sibling N-blocks
// of the same M-tile have adjacent bids and are co-resident, so the second one
// reads its A-slab from L2 instead of DRAM.
// CTA tile 128x128xBK16, 8 warps, each warp 64x32 via 4x4 m16n8k8 frags.
// rowscale applied at fragment-load time; split must be a multiple of 16
// (HOGSPL = 4464 = 279*16) so the hog/cov select is uniform per K-tile.
__global__ __launch_bounds__(256, 2)
void gemm_tf32_kernel(const float* __restrict__ A, const float* __restrict__ B,
                      float* __restrict__ C, int M, int N, int K,
                      const float* __restrict__ rowscale, int split) {
    // stride 136 (8-word pad): frag loads bank = (8*tg + gid) % 32 -> conflict-free
    __shared__ uint32_t As[2][16][136];   // raw fp32 bits, [buf][k][m]
    __shared__ uint32_t Bs[2][16][136];   // raw fp32 bits, [buf][k][n]

    const int tid  = threadIdx.x;
    const int m0   = blockIdx.y * 128;    // M-block on y
    const int n0   = blockIdx.x * 128;    // N-block on x (adjacent bids share A)
    const int lane = tid & 31;
    const int wid  = tid >> 5;
    const int warp_m = wid >> 2;   // 0..1  -> 64 rows
    const int warp_n = wid & 3;    // 0..3  -> 32 cols
    const int gid  = lane >> 2;    // 0..7
    const int tg   = lane & 3;     // 0..3

    // loader mapping: half-warp-row: 16 lanes cover 16 consecutive k of one row
    const int arow = tid >> 4;     // 0..15
    const int ak   = tid & 15;     // 0..15

    const uint32_t asBase = (uint32_t)__cvta_generic_to_shared(&As[0][0][0]);
    const uint32_t bsBase = (uint32_t)__cvta_generic_to_shared(&Bs[0][0][0]);

    // per-thread row scales for the 8 M-rows this thread's A-frags touch
    float scH[4][2], scC[4][2];
    #pragma unroll
    for (int i = 0; i < 4; i++) {
        #pragma unroll
        for (int r = 0; r < 2; r++) {
            int m = m0 + warp_m * 64 + i * 16 + gid + r * 8;
            bool ok = (rowscale != nullptr) && (m < M);
            scH[i][r] = ok ? rowscale[2*m]   : 1.f;
            scC[i][r] = ok ? rowscale[2*m+1] : 1.f;
        }
    }

    float acc[4][4][4];
    #pragma unroll
    for (int i = 0; i < 4; i++)
        #pragma unroll
        for (int j = 0; j < 4; j++)
            #pragma unroll
            for (int r = 0; r < 4; r++) acc[i][j][r] = 0.f;

    const int ntiles = (K + 15) >> 4;

    // issue async loads for tile t into buffer buf
    auto issue_tile = [&](int buf, int t) {
        const int k0 = t << 4;
        // A: 128 rows x 16 k, 8 x 4B per thread, zfill OOB
        const int kg = k0 + ak;
        #pragma unroll
        for (int p = 0; p < 8; p++) {
            int row = arow + p * 16;
            int m   = m0 + row;
            uint32_t dst = asBase + (uint32_t)(((buf * 16 + ak) * 136 + row) * 4);
            int sz = (m < M && kg < K) ? 4 : 0;
            cp_async4(dst, A + (size_t)m * K + kg, sz);
        }
        // B: 16 k x 128 n, 2 x 16B per thread, zfill OOB k
        #pragma unroll
        for (int l = 0; l < 2; l++) {
            int idx = tid + l * 256;
            int row = idx >> 5;
            int c4  = (idx & 31) << 2;
            int kg2 = k0 + row;
            uint32_t dst = bsBase + (uint32_t)(((buf * 16 + row) * 136 + c4) * 4);
            int sz = (kg2 < K) ? 16 : 0;
            cp_async16(dst, B + (size_t)kg2 * N + n0 + c4, sz);
        }
        cp_commit();
    };

    issue_tile(0, 0);

    for (int t = 0; t < ntiles; t++) {
        if (t + 1 < ntiles) {
            issue_tile((t + 1) & 1, t + 1);
            asm volatile("cp.async.wait_group 1;" ::: "memory");
        } else {
            asm volatile("cp.async.wait_group 0;" ::: "memory");
        }
        __syncthreads();

        const int buf = t & 1;
        const bool hog = ((t << 4) < split);
        float sA0[4], sA1[4];
        #pragma unroll
        for (int i = 0; i < 4; i++) {
            sA0[i] = hog ? scH[i][0] : scC[i][0];
            sA1[i] = hog ? scH[i][1] : scC[i][1];
        }

        #pragma unroll
        for (int ks = 0; ks < 16; ks += 8) {
            uint32_t afrag[4][4];
            #pragma unroll
            for (int i = 0; i < 4; i++) {
                int mb = warp_m * 64 + i * 16;
                afrag[i][0] = f2tf32(__uint_as_float(As[buf][ks + tg    ][mb + gid    ]) * sA0[i]);
                afrag[i][1] = f2tf32(__uint_as_float(As[buf][ks + tg    ][mb + gid + 8]) * sA1[i]);
                afrag[i][2] = f2tf32(__uint_as_float(As[buf][ks + tg + 4][mb + gid    ]) * sA0[i]);
                afrag[i][3] = f2tf32(__uint_as_float(As[buf][ks + tg + 4][mb + gid + 8]) * sA1[i]);
            }
            uint32_t bfrag[4][2];
            #pragma unroll
            for (int j = 0; j < 4; j++) {
                int nb = warp_n * 32 + j * 8;
                bfrag[j][0] = f2tf32(__uint_as_float(Bs[buf][ks + tg    ][nb + gid]));
                bfrag[j][1] = f2tf32(__uint_as_float(Bs[buf][ks + tg + 4][nb + gid]));
            }
            #pragma unroll
            for (int i = 0; i < 4; i++)
                #pragma unroll
                for (int j = 0; j < 4; j++)
                    mma_tf32(acc[i][j], afrag[i], bfrag[j]);
        }
        __syncthreads();   // protect buf from being overwritten by next issue
    }

    // ---- epilogue: C frag layout -> gmem ----
    #pragma unroll
    for (int i = 0; i < 4; i++) {
        int r0 = m0 + warp_m * 64 + i * 16 + gid;
        int r1 = r0 + 8;
        #pragma unroll
        for (int j = 0; j < 4; j++) {
            int c = n0 + warp_n * 32 + j * 8 + tg * 2;
            if (r0 < M) *(float2*)(C + (size_t)r0 * N + c) = make_float2(acc[i][j][0], acc[i][j][1]);
            if (r1 < M) *(float2*)(C + (size_t)r1 * N + c) = make_float2(acc[i][j][2], acc[i][j][3]);
        }
    }
}

// ---------------- per-node attention scalars ----------------
__global__ void alpha_kernel(const float* __restrict__ h, const float* __restrict__ asrc,
                             const float* __restrict__ adst, float* __restrict__ oas,
                             float* __restrict__ oad, int n, int heads) {
    int warp = (blockIdx.x * blockDim.x + threadIdx.x) >> 5;
    int lane = threadIdx.x & 31;
    if (warp >= n) return;
    const float* hr = h + (size_t)warp * heads * HID;
    for (int hh = 0; hh < heads; hh++) {
        float s = 0.f, d = 0.f;
        #pragma unroll
        for (int k = lane; k < HID; k += 32) {
            float v = hr[hh*HID + k];
            s += v * asrc[hh*HID + k];
            d += v * adst[hh*HID + k];
        }
        #pragma unroll
        for (int o = 16; o; o >>= 1) {
            s += __shfl_down_sync(0xffffffffu, s, o);
            d += __shfl_down_sync(0xffffffffu, d, o);
        }
        if (lane == 0) { oas[warp*heads + hh] = s; oad[warp*heads + hh] = d; }
    }
}

// ---------------- edge pass A: e = leaky(as[src]+ad[dst]); segment max over dst ----------------
__global__ void edge_max_kernel(const int* __restrict__ ei, int ne, int etot,
                                const float* __restrict__ as, const float* __restrict__ ad,
                                float* __restrict__ estore, float* __restrict__ mbuf, int heads) {
    int i = blockIdx.x * blockDim.x + threadIdx.x;
    if (i >= etot * heads) return;
    int e = i / heads, h = i - e * heads;
    int s, d;
    if (e < ne) { s = ei[e]; d = ei[ne + e]; } else { s = d = e - ne; }
    float v = as[s*heads + h] + ad[d*heads + h];
    v = v > 0.f ? v : 0.2f * v;
    estore[i] = v;
    atomicMaxF(&mbuf[d*heads + h], v);
}

// ---------------- edge pass B: e' = exp(e - m[dst]); segment sum over dst ----------------
__global__ void edge_exp_kernel(const int* __restrict__ ei, int ne, int etot,
                                float* __restrict__ estore, const float* __restrict__ mbuf,
                                float* __restrict__ den, int heads) {
    int i = blockIdx.x * blockDim.x + threadIdx.x;
    if (i >= etot * heads) return;
    int e = i / heads, h = i - e * heads;
    int d;
    if (e < ne) { d = ei[ne + e]; } else { d = e - ne; }
    float ex = __expf(estore[i] - mbuf[d*heads + h]);
    estore[i] = ex;
    atomicAdd(&den[d*heads + h], ex);
}

// ---------------- edge pass C: out[dst] += alpha * h[src]  (warp per edge, v4 RED) ------------
__global__ void edge_scatter_kernel(const int* __restrict__ ei, int ne, int etot,
                                    const float* __restrict__ estore, const float* __restrict__ den,
                                    const float* __restrict__ h, float* __restrict__ out, int heads) {
    int warp = (blockIdx.x * blockDim.x + threadIdx.x) >> 5;
    int lane = threadIdx.x & 31;
    if (warp >= etot) return;
    int s, d;
    if (warp < ne) { s = ei[warp]; d = ei[ne + warp]; } else { s = d = warp - ne; }
    int D = heads * HID;
    const float* hr = h + (size_t)s * D;
    float* orow = out + (size_t)d * D;
    for (int hh = 0; hh < heads; hh++) {
        float a = estore[warp*heads + hh] / (den[d*heads + hh] + 1e-16f);
        int base = hh*HID + lane*4;
        float4 v = *(const float4*)(hr + base);
        v.x *= a; v.y *= a; v.z *= a; v.w *= a;
        red_add_v4(orow + base, v);
    }
}

// ---------------- elementwise bias + relu ----------------
__global__ void bias_relu_kernel(const float* __restrict__ in, const float* __restrict__ b,
                                 float* __restrict__ out, size_t total, int Dmask) {
    size_t i = (size_t)blockIdx.x * blockDim.x + threadIdx.x;
    if (i >= total) return;
    out[i] = fmaxf(in[i] + b[i & Dmask], 0.f);
}

// ---------------- pooling: mean over batch segments (warp per node) ----------------
__global__ void pool_kernel(const float* __restrict__ out2, const float* __restrict__ b2,
                            const int* __restrict__ batch, float* __restrict__ sums,
                            float* __restrict__ cnt, int n) {
    int warp = (blockIdx.x * blockDim.x + threadIdx.x) >> 5;
    int lane = threadIdx.x & 31;
    if (warp >= n) return;
    int b = batch[warp];
    int base = lane * 4;
    float4 v  = *(const float4*)(out2 + (size_t)warp * HID + base);
    float4 bb = *(const float4*)(b2 + base);
    v.x = fmaxf(v.x + bb.x, 0.f);
    v.y = fmaxf(v.y + bb.y, 0.f);
    v.z = fmaxf(v.z + bb.z, 0.f);
    v.w = fmaxf(v.w + bb.w, 0.f);
    red_add_v4(sums + (size_t)b * HID + base, v);
    if (lane == 0) atomicAdd(&cnt[b], 1.0f);
}

// ---------------- classifier: relu(pooled@Wc1+bc1)@Wc2+bc2 ----------------
__global__ void classifier_kernel(const float* __restrict__ sums, const float* __restrict__ cnt,
                                  const float* __restrict__ Wc1, const float* __restrict__ bc1,
                                  const float* __restrict__ Wc2, const float* __restrict__ bc2,
                                  float* __restrict__ out) {
    int g = blockIdx.x;
    int t = threadIdx.x;        // 64 threads
    __shared__ float p[128], z[64];
    float c = fmaxf(cnt[g], 1.0f);
    p[t]      = sums[g*128 + t] / c;
    p[t + 64] = sums[g*128 + 64 + t] / c;
    __syncthreads();
    float acc = bc1[t];
    #pragma unroll 8
    for (int k = 0; k < 128; k++) acc += p[k] * Wc1[k*64 + t];
    z[t] = fmaxf(acc, 0.f);
    __syncthreads();
    if (t < 4) {
        float a = bc2[t];
        #pragma unroll 8
        for (int j = 0; j < 64; j++) a += z[j] * Wc2[j*4 + t];
        out[g*4 + t] = a;
    }
}

// ---------------- launch ----------------
extern "C" void kernel_launch(void* const* d_in, const int* in_sizes, int n_in,
                              void* d_out, int out_size) {
    const float* x       = (const float*)d_in[0];
    const int*   ei      = (const int*)  d_in[1];
    const int*   batch   = (const int*)  d_in[2];
    const float* attn_W  = (const float*)d_in[3];
    const float* attn_b  = (const float*)d_in[4];
    const float* W1      = (const float*)d_in[5];
    const float* a_src1  = (const float*)d_in[6];
    const float* a_dst1  = (const float*)d_in[7];
    const float* b1      = (const float*)d_in[8];
    const float* W2      = (const float*)d_in[9];
    const float* a_src2  = (const float*)d_in[10];
    const float* a_dst2  = (const float*)d_in[11];
    const float* b2      = (const float*)d_in[12];
    const float* Wc1     = (const float*)d_in[13];
    const float* bc1     = (const float*)d_in[14];
    const float* Wc2     = (const float*)d_in[15];
    const float* bc2     = (const float*)d_in[16];
    float* out = (float*)d_out;

    int n    = in_sizes[2];          // 30000
    int ne   = in_sizes[1] / 2;      // 960000
    int etot = ne + n;               // 990000
    int K    = in_sizes[0] / n;      // 4527

    float* base;
    cudaGetSymbolAddress((void**)&base, g_buf);
    float* attn = base + OFF_ATTN;
    float* h1   = base + OFF_H1;
    float* as1  = base + OFF_AS1;
    float* ad1  = base + OFF_AD1;
    float* e1   = base + OFF_E1;
    float* m1   = base + OFF_M1;
    float* den1 = base + OFF_DEN1;
    float* out1 = base + OFF_OUT1;
    float* x2   = base + OFF_X2;
    float* h2   = base + OFF_H2;
    float* as2  = base + OFF_AS2;
    float* ad2  = base + OFF_AD2;
    float* e2   = base + OFF_E2;
    float* m2   = base + OFF_M2;
    float* den2 = base + OFF_DEN2;
    float* out2 = base + OFF_OUT2;
    float* pool = base + OFF_POOL;
    float* cnt  = base + OFF_CNT;

    // 0) init accumulators
    init_kernel<<<(n * 256) / 256, 256>>>(out1, out2, m1, den1, m2, den2, pool, cnt);

    // 1) attention gate softmax
    attn_kernel<<<(n + 7) / 8, 256>>>(x, attn_W, attn_b, attn, n, K);

    // 2) GEMM1: h1 = fused @ W1  (row-scaled A fused in tf32 GEMM)
    {
        dim3 grid(2, (n + 127) / 128);   // x = N-blocks, y = M-blocks
        gemm_tf32_kernel<<<grid, 256>>>(x, W1, h1, n, 2*HID, K, attn, HOGSPL);
    }

    // 3) layer-1 attention scalars
    alpha_kernel<<<(n + 7) / 8, 256>>>(h1, a_src1, a_dst1, as1, ad1, n, 2);

    // 4) layer-1 edge softmax + aggregation
    edge_max_kernel<<<(etot*2 + 255) / 256, 256>>>(ei, ne, etot, as1, ad1, e1, m1, 2);
    edge_exp_kernel<<<(etot*2 + 255) / 256, 256>>>(ei, ne, etot, e1, m1, den1, 2);
    edge_scatter_kernel<<<(etot + 7) / 8, 256>>>(ei, ne, etot, e1, den1, h1, out1, 2);

    // 5) x2 = relu(out1 + b1)
    bias_relu_kernel<<<(n * 256 + 255) / 256, 256>>>(out1, b1, x2, (size_t)n * 256, 255);

    // 6) GEMM2: h2 = x2 @ W2 (tf32)
    {
        dim3 grid(1, (n + 127) / 128);
        gemm_tf32_kernel<<<grid, 256>>>(x2, W2, h2, n, HID, 2*HID, nullptr, 0);
    }

    // 7) layer-2 attention scalars
    alpha_kernel<<<(n + 7) / 8, 256>>>(h2, a_src2, a_dst2, as2, ad2, n, 1);

    // 8) layer-2 edge softmax + aggregation
    edge_max_kernel<<<(etot + 255) / 256, 256>>>(ei, ne, etot, as2, ad2, e2, m2, 1);
    edge_exp_kernel<<<(etot + 255) / 256, 256>>>(ei, ne, etot, e2, m2, den2, 1);
    edge_scatter_kernel<<<(etot + 7) / 8, 256>>>(ei, ne, etot, e2, den2, h2, out2, 1);

    // 9) pooling: mean over graphs of relu(out2 + b2)
    pool_kernel<<<(n + 7) / 8, 256>>>(out2, b2, batch, pool, cnt, n);

    // 10) classifier head
    classifier_kernel<<<NG, 64>>>(pool, cnt, Wc1, bc1, Wc2, bc2, out);
}

// round 12
// speedup vs baseline: 2.6596x; 1.4251x over previous
#include <cuda_runtime.h>
#include <cuda_fp16.h>
#include <math.h>
#include <stdint.h>

// Problem constants (fixed by dataset)
#define NN     30000
#define NEDGE  960000
#define ETOT   990000      // + self loops
#define INDIM  4527
#define LDXH   4528        // padded fp16 row stride (16B aligned, pad col zeroed)
#define HOGSPL 4464
#define HID    128
#define NG     64

// ---------------- scratch (static device memory; no allocation) ----------------
static constexpr size_t OFF_ATTN = 0;                         // (unused now)
static constexpr size_t OFF_H1   = OFF_ATTN + 2UL*NN;         // 30000*256
static constexpr size_t OFF_AS1  = OFF_H1   + 256UL*NN;
static constexpr size_t OFF_AD1  = OFF_AS1  + 2UL*NN;
static constexpr size_t OFF_E1   = OFF_AD1  + 2UL*NN;         // 990000*2
static constexpr size_t OFF_M1   = OFF_E1   + 2UL*ETOT;
static constexpr size_t OFF_DEN1 = OFF_M1   + 2UL*NN;
static constexpr size_t OFF_OUT1 = OFF_DEN1 + 2UL*NN;         // 30000*256
static constexpr size_t OFF_X2   = OFF_OUT1 + 256UL*NN;       // (unused now)
static constexpr size_t OFF_H2   = OFF_X2   + 256UL*NN;       // 30000*128
static constexpr size_t OFF_AS2  = OFF_H2   + 128UL*NN;
static constexpr size_t OFF_AD2  = OFF_AS2  + 1UL*NN;
static constexpr size_t OFF_E2   = OFF_AD2  + 1UL*NN;         // 990000
static constexpr size_t OFF_M2   = OFF_E2   + 1UL*ETOT;
static constexpr size_t OFF_DEN2 = OFF_M2   + 1UL*NN;
static constexpr size_t OFF_OUT2 = OFF_DEN2 + 1UL*NN;         // 30000*128
static constexpr size_t OFF_POOL = OFF_OUT2 + 128UL*NN;       // 64*128
static constexpr size_t OFF_CNT  = OFF_POOL + 128UL*NG;       // 64
static constexpr size_t TOTAL_F  = OFF_CNT  + NG;

__device__ float  g_buf[TOTAL_F];
__device__ __half g_xh [(size_t)NN * LDXH];     // gated x, fp16, padded
__device__ __half g_w1t[(size_t)256 * LDXH];    // W1^T fp16 [256][4528]
__device__ __half g_w2t[(size_t)128 * 256];     // W2^T fp16 [128][256]
__device__ __half g_x2h[(size_t)NN * 256];      // relu(out1+b1) fp16

// ---------------- helpers ----------------
__device__ __forceinline__ void atomicMaxF(float* addr, float v) {
    if (v >= 0.0f) atomicMax((int*)addr, __float_as_int(v));
    else           atomicMin((unsigned int*)addr, __float_as_uint(v));
}

__device__ __forceinline__ void red_add_v4(float* p, float4 v) {
    asm volatile("red.global.add.v4.f32 [%0], {%1,%2,%3,%4};"
                 :: "l"(p), "f"(v.x), "f"(v.y), "f"(v.z), "f"(v.w) : "memory");
}

__device__ __forceinline__ void mma_f16(float* d, const uint32_t* a, const uint32_t* b) {
    asm volatile(
        "mma.sync.aligned.m16n8k16.row.col.f32.f16.f16.f32 "
        "{%0,%1,%2,%3}, {%4,%5,%6,%7}, {%8,%9}, {%0,%1,%2,%3};"
        : "+f"(d[0]), "+f"(d[1]), "+f"(d[2]), "+f"(d[3])
        : "r"(a[0]), "r"(a[1]), "r"(a[2]), "r"(a[3]), "r"(b[0]), "r"(b[1]));
}

__device__ __forceinline__ void ldsm_x4(uint32_t& r0, uint32_t& r1, uint32_t& r2, uint32_t& r3,
                                        uint32_t addr) {
    asm volatile("ldmatrix.sync.aligned.m8n8.x4.shared.b16 {%0,%1,%2,%3}, [%4];"
                 : "=r"(r0), "=r"(r1), "=r"(r2), "=r"(r3) : "r"(addr));
}

__device__ __forceinline__ void cp_async16(uint32_t smem_dst, const void* gsrc, int sz) {
    asm volatile("cp.async.cg.shared.global [%0], [%1], 16, %2;"
                 :: "r"(smem_dst), "l"(gsrc), "r"(sz));
}
__device__ __forceinline__ void cp_commit() {
    asm volatile("cp.async.commit_group;");
}

// ---------------- init (zero / -inf the accumulators each launch) ----------------
__global__ void init_kernel(float* out1, float* out2, float* m1, float* den1,
                            float* m2, float* den2, float* pool, float* cnt) {
    size_t i = (size_t)blockIdx.x * blockDim.x + threadIdx.x;   // exactly 7,680,000 threads
    out1[i] = 0.0f;
    if (i < 128UL*NN) out2[i] = 0.0f;
    if (i < 2UL*NN)  { m1[i] = -INFINITY; den1[i] = 0.0f; }
    if (i < 1UL*NN)  { m2[i] = -INFINITY; den2[i] = 0.0f; }
    if (i < 128UL*NG) pool[i] = 0.0f;
    if (i < NG)       cnt[i] = 0.0f;
}

// ---------------- attn softmax fused with fp16 gating: xh = gate(x) ----------------
__global__ void attn_gate_kernel(const float* __restrict__ x, const float* __restrict__ aW,
                                 const float* __restrict__ ab, __half* __restrict__ xh,
                                 int n, int K, int split) {
    int warp = (blockIdx.x * blockDim.x + threadIdx.x) >> 5;
    int lane = threadIdx.x & 31;
    if (warp >= n) return;
    const float* row = x + (size_t)warp * K;
    float l0 = 0.f, l1 = 0.f;
    for (int k = lane; k < K; k += 32) {
        float v = row[k];
        l0 += v * aW[2*k];
        l1 += v * aW[2*k+1];
    }
    #pragma unroll
    for (int o = 16; o; o >>= 1) {
        l0 += __shfl_down_sync(0xffffffffu, l0, o);
        l1 += __shfl_down_sync(0xffffffffu, l1, o);
    }
    float s0 = 0.f, s1 = 0.f;
    if (lane == 0) {
        l0 += ab[0]; l1 += ab[1];
        float m  = fmaxf(l0, l1);
        float e0 = __expf(l0 - m), e1 = __expf(l1 - m);
        float s  = e0 + e1;
        s0 = e0 / s; s1 = e1 / s;
    }
    s0 = __shfl_sync(0xffffffffu, s0, 0);
    s1 = __shfl_sync(0xffffffffu, s1, 0);
    __half* orow = xh + (size_t)warp * LDXH;
    for (int k = lane; k < LDXH; k += 32) {
        float v = 0.f;
        if (k < K) v = row[k] * (k < split ? s0 : s1);
        orow[k] = __float2half(v);
    }
}

// ---------------- weight transpose+convert ----------------
__global__ void w1t_kernel(const float* __restrict__ W1, __half* __restrict__ w1t) {
    int idx = blockIdx.x * blockDim.x + threadIdx.x;
    if (idx >= 256 * LDXH) return;
    int nn = idx / LDXH, k = idx % LDXH;
    float v = (k < INDIM) ? W1[(size_t)k * 256 + nn] : 0.f;
    w1t[idx] = __float2half(v);
}
__global__ void w2t_kernel(const float* __restrict__ W2, __half* __restrict__ w2t) {
    int idx = blockIdx.x * blockDim.x + threadIdx.x;
    if (idx >= 128 * 256) return;
    int nn = idx / 256, k = idx % 256;
    w2t[idx] = __float2half(W2[(size_t)k * 128 + nn]);
}

// ---------------- fp16 tensor-core GEMM, cp.async double-buffered ----------------
// C[M,N] (fp32) = A[M,K] (fp16, row stride lda) @ Bt[N,K]^T (fp16, row stride ldb)
// CTA tile 128x128xBK32, 8 warps, each warp 64x32 via 4x4 m16n8k16 frags + ldmatrix.
// smem rows 40 halfs = 80B: ldmatrix row start banks (20r mod 32) all distinct -> conflict-free.
__global__ __launch_bounds__(256, 2)
void gemm_f16_kernel(const __half* __restrict__ A, int lda,
                     const __half* __restrict__ Bt, int ldb,
                     float* __restrict__ C, int M, int N, int K) {
    __shared__ __align__(16) __half As[2][128][40];
    __shared__ __align__(16) __half Bs[2][128][40];

    const int tid  = threadIdx.x;
    const int m0   = blockIdx.y * 128;    // M-block on y
    const int n0   = blockIdx.x * 128;    // N-block on x (adjacent bids share A via L2)
    const int lane = tid & 31;
    const int wid  = tid >> 5;
    const int warp_m = wid >> 2;   // 0..1
    const int warp_n = wid & 3;    // 0..3
    const int gid  = lane >> 2;
    const int tg   = lane & 3;

    float acc[4][4][4];
    #pragma unroll
    for (int i = 0; i < 4; i++)
        #pragma unroll
        for (int j = 0; j < 4; j++)
            #pragma unroll
            for (int r = 0; r < 4; r++) acc[i][j][r] = 0.f;

    const int ntiles = (K + 31) >> 5;

    auto issue_tile = [&](int buf, int t) {
        const int k0 = t << 5;
        #pragma unroll
        for (int l = 0; l < 2; l++) {
            int c   = tid + l * 256;      // 0..511
            int row = c >> 2;             // 0..127
            int q   = c & 3;              // 16B chunk within 64B row
            int kg  = k0 + q * 8;
            {   // A chunk
                int m = m0 + row;
                uint32_t dst = (uint32_t)__cvta_generic_to_shared(&As[buf][row][q * 8]);
                int sz = (m < M && kg < K) ? 16 : 0;
                cp_async16(dst, A + (size_t)m * lda + kg, sz);
            }
            {   // B chunk (n rows always valid: N is a multiple of 128 here)
                int nn = n0 + row;
                uint32_t dst = (uint32_t)__cvta_generic_to_shared(&Bs[buf][row][q * 8]);
                int sz = (kg < K) ? 16 : 0;
                cp_async16(dst, Bt + (size_t)nn * ldb + kg, sz);
            }
        }
        cp_commit();
    };

    issue_tile(0, 0);

    for (int t = 0; t < ntiles; t++) {
        if (t + 1 < ntiles) {
            issue_tile((t + 1) & 1, t + 1);
            asm volatile("cp.async.wait_group 1;" ::: "memory");
        } else {
            asm volatile("cp.async.wait_group 0;" ::: "memory");
        }
        __syncthreads();

        const int buf = t & 1;
        #pragma unroll
        for (int ks = 0; ks < 32; ks += 16) {
            // A frags: lanes 0-7 rows 0-7 @k, 8-15 rows 8-15 @k, 16-23 rows 0-7 @k+8, 24-31 rows 8-15 @k+8
            uint32_t a[4][4];
            #pragma unroll
            for (int i = 0; i < 4; i++) {
                int mrow = warp_m * 64 + i * 16 + (lane & 15);
                int kcol = ks + ((lane >> 4) << 3);
                uint32_t ad = (uint32_t)__cvta_generic_to_shared(&As[buf][mrow][kcol]);
                ldsm_x4(a[i][0], a[i][1], a[i][2], a[i][3], ad);
            }
            // B frags: per jp, matrices (n j*8..+7 @k), (same @k+8), (n (j+1)*8 @k), (@k+8)
            uint32_t b[4][2];
            #pragma unroll
            for (int jp = 0; jp < 2; jp++) {
                int sel  = lane >> 3;   // 0..3
                int nrow = warp_n * 32 + jp * 16 + (lane & 7) + ((sel >> 1) << 3);
                int kcol = ks + ((sel & 1) << 3);
                uint32_t ad = (uint32_t)__cvta_generic_to_shared(&Bs[buf][nrow][kcol]);
                uint32_t r0, r1, r2, r3;
                ldsm_x4(r0, r1, r2, r3, ad);
                b[jp*2][0] = r0; b[jp*2][1] = r1;
                b[jp*2+1][0] = r2; b[jp*2+1][1] = r3;
            }
            #pragma unroll
            for (int i = 0; i < 4; i++)
                #pragma unroll
                for (int j = 0; j < 4; j++)
                    mma_f16(acc[i][j], a[i], b[j]);
        }
        __syncthreads();   // protect buf from next issue
    }

    // ---- epilogue ----
    #pragma unroll
    for (int i = 0; i < 4; i++) {
        int r0 = m0 + warp_m * 64 + i * 16 + gid;
        int r1 = r0 + 8;
        #pragma unroll
        for (int j = 0; j < 4; j++) {
            int c = n0 + warp_n * 32 + j * 8 + tg * 2;
            if (r0 < M) *(float2*)(C + (size_t)r0 * N + c) = make_float2(acc[i][j][0], acc[i][j][1]);
            if (r1 < M) *(float2*)(C + (size_t)r1 * N + c) = make_float2(acc[i][j][2], acc[i][j][3]);
        }
    }
}

// ---------------- per-node attention scalars ----------------
__global__ void alpha_kernel(const float* __restrict__ h, const float* __restrict__ asrc,
                             const float* __restrict__ adst, float* __restrict__ oas,
                             float* __restrict__ oad, int n, int heads) {
    int warp = (blockIdx.x * blockDim.x + threadIdx.x) >> 5;
    int lane = threadIdx.x & 31;
    if (warp >= n) return;
    const float* hr = h + (size_t)warp * heads * HID;
    for (int hh = 0; hh < heads; hh++) {
        float s = 0.f, d = 0.f;
        #pragma unroll
        for (int k = lane; k < HID; k += 32) {
            float v = hr[hh*HID + k];
            s += v * asrc[hh*HID + k];
            d += v * adst[hh*HID + k];
        }
        #pragma unroll
        for (int o = 16; o; o >>= 1) {
            s += __shfl_down_sync(0xffffffffu, s, o);
            d += __shfl_down_sync(0xffffffffu, d, o);
        }
        if (lane == 0) { oas[warp*heads + hh] = s; oad[warp*heads + hh] = d; }
    }
}

// ---------------- edge pass A ----------------
__global__ void edge_max_kernel(const int* __restrict__ ei, int ne, int etot,
                                const float* __restrict__ as, const float* __restrict__ ad,
                                float* __restrict__ estore, float* __restrict__ mbuf, int heads) {
    int i = blockIdx.x * blockDim.x + threadIdx.x;
    if (i >= etot * heads) return;
    int e = i / heads, h = i - e * heads;
    int s, d;
    if (e < ne) { s = ei[e]; d = ei[ne + e]; } else { s = d = e - ne; }
    float v = as[s*heads + h] + ad[d*heads + h];
    v = v > 0.f ? v : 0.2f * v;
    estore[i] = v;
    atomicMaxF(&mbuf[d*heads + h], v);
}

// ---------------- edge pass B ----------------
__global__ void edge_exp_kernel(const int* __restrict__ ei, int ne, int etot,
                                float* __restrict__ estore, const float* __restrict__ mbuf,
                                float* __restrict__ den, int heads) {
    int i = blockIdx.x * blockDim.x + threadIdx.x;
    if (i >= etot * heads) return;
    int e = i / heads, h = i - e * heads;
    int d;
    if (e < ne) { d = ei[ne + e]; } else { d = e - ne; }
    float ex = __expf(estore[i] - mbuf[d*heads + h]);
    estore[i] = ex;
    atomicAdd(&den[d*heads + h], ex);
}

// ---------------- edge pass C ----------------
__global__ void edge_scatter_kernel(const int* __restrict__ ei, int ne, int etot,
                                    const float* __restrict__ estore, const float* __restrict__ den,
                                    const float* __restrict__ h, float* __restrict__ out, int heads) {
    int warp = (blockIdx.x * blockDim.x + threadIdx.x) >> 5;
    int lane = threadIdx.x & 31;
    if (warp >= etot) return;
    int s, d;
    if (warp < ne) { s = ei[warp]; d = ei[ne + warp]; } else { s = d = warp - ne; }
    int D = heads * HID;
    const float* hr = h + (size_t)s * D;
    float* orow = out + (size_t)d * D;
    for (int hh = 0; hh < heads; hh++) {
        float a = estore[warp*heads + hh] / (den[d*heads + hh] + 1e-16f);
        int base = hh*HID + lane*4;
        float4 v = *(const float4*)(hr + base);
        v.x *= a; v.y *= a; v.z *= a; v.w *= a;
        red_add_v4(orow + base, v);
    }
}

// ---------------- bias + relu -> fp16 ----------------
__global__ void bias_relu_h_kernel(const float* __restrict__ in, const float* __restrict__ b,
                                   __half* __restrict__ out, size_t total, int Dmask) {
    size_t i = (size_t)blockIdx.x * blockDim.x + threadIdx.x;
    if (i >= total) return;
    out[i] = __float2half(fmaxf(in[i] + b[i & Dmask], 0.f));
}

// ---------------- pooling ----------------
__global__ void pool_kernel(const float* __restrict__ out2, const float* __restrict__ b2,
                            const int* __restrict__ batch, float* __restrict__ sums,
                            float* __restrict__ cnt, int n) {
    int warp = (blockIdx.x * blockDim.x + threadIdx.x) >> 5;
    int lane = threadIdx.x & 31;
    if (warp >= n) return;
    int b = batch[warp];
    int base = lane * 4;
    float4 v  = *(const float4*)(out2 + (size_t)warp * HID + base);
    float4 bb = *(const float4*)(b2 + base);
    v.x = fmaxf(v.x + bb.x, 0.f);
    v.y = fmaxf(v.y + bb.y, 0.f);
    v.z = fmaxf(v.z + bb.z, 0.f);
    v.w = fmaxf(v.w + bb.w, 0.f);
    red_add_v4(sums + (size_t)b * HID + base, v);
    if (lane == 0) atomicAdd(&cnt[b], 1.0f);
}

// ---------------- classifier ----------------
__global__ void classifier_kernel(const float* __restrict__ sums, const float* __restrict__ cnt,
                                  const float* __restrict__ Wc1, const float* __restrict__ bc1,
                                  const float* __restrict__ Wc2, const float* __restrict__ bc2,
                                  float* __restrict__ out) {
    int g = blockIdx.x;
    int t = threadIdx.x;        // 64 threads
    __shared__ float p[128], z[64];
    float c = fmaxf(cnt[g], 1.0f);
    p[t]      = sums[g*128 + t] / c;
    p[t + 64] = sums[g*128 + 64 + t] / c;
    __syncthreads();
    float acc = bc1[t];
    #pragma unroll 8
    for (int k = 0; k < 128; k++) acc += p[k] * Wc1[k*64 + t];
    z[t] = fmaxf(acc, 0.f);
    __syncthreads();
    if (t < 4) {
        float a = bc2[t];
        #pragma unroll 8
        for (int j = 0; j < 64; j++) a += z[j] * Wc2[j*4 + t];
        out[g*4 + t] = a;
    }
}

// ---------------- launch ----------------
extern "C" void kernel_launch(void* const* d_in, const int* in_sizes, int n_in,
                              void* d_out, int out_size) {
    const float* x       = (const float*)d_in[0];
    const int*   ei      = (const int*)  d_in[1];
    const int*   batch   = (const int*)  d_in[2];
    const float* attn_W  = (const float*)d_in[3];
    const float* attn_b  = (const float*)d_in[4];
    const float* W1      = (const float*)d_in[5];
    const float* a_src1  = (const float*)d_in[6];
    const float* a_dst1  = (const float*)d_in[7];
    const float* b1      = (const float*)d_in[8];
    const float* W2      = (const float*)d_in[9];
    const float* a_src2  = (const float*)d_in[10];
    const float* a_dst2  = (const float*)d_in[11];
    const float* b2      = (const float*)d_in[12];
    const float* Wc1     = (const float*)d_in[13];
    const float* bc1     = (const float*)d_in[14];
    const float* Wc2     = (const float*)d_in[15];
    const float* bc2     = (const float*)d_in[16];
    float* out = (float*)d_out;

    int n    = in_sizes[2];          // 30000
    int ne   = in_sizes[1] / 2;      // 960000
    int etot = ne + n;               // 990000
    int K    = in_sizes[0] / n;      // 4527

    float* base;
    cudaGetSymbolAddress((void**)&base, g_buf);
    __half *xh, *w1t, *w2t, *x2h;
    cudaGetSymbolAddress((void**)&xh,  g_xh);
    cudaGetSymbolAddress((void**)&w1t, g_w1t);
    cudaGetSymbolAddress((void**)&w2t, g_w2t);
    cudaGetSymbolAddress((void**)&x2h, g_x2h);

    float* h1   = base + OFF_H1;
    float* as1  = base + OFF_AS1;
    float* ad1  = base + OFF_AD1;
    float* e1   = base + OFF_E1;
    float* m1   = base + OFF_M1;
    float* den1 = base + OFF_DEN1;
    float* out1 = base + OFF_OUT1;
    float* h2   = base + OFF_H2;
    float* as2  = base + OFF_AS2;
    float* ad2  = base + OFF_AD2;
    float* e2   = base + OFF_E2;
    float* m2   = base + OFF_M2;
    float* den2 = base + OFF_DEN2;
    float* out2 = base + OFF_OUT2;
    float* pool = base + OFF_POOL;
    float* cnt  = base + OFF_CNT;

    // 0) init accumulators
    init_kernel<<<(n * 256) / 256, 256>>>(out1, out2, m1, den1, m2, den2, pool, cnt);

    // 0b) weight transpose+convert (fp16)
    w1t_kernel<<<(256 * LDXH + 255) / 256, 256>>>(W1, w1t);
    w2t_kernel<<<(128 * 256 + 255) / 256, 256>>>(W2, w2t);

    // 1) attention softmax fused with fp16 gating: xh = gate(x)
    attn_gate_kernel<<<(n + 7) / 8, 256>>>(x, attn_W, attn_b, xh, n, K, HOGSPL);

    // 2) GEMM1: h1 = xh @ W1 (fp16 tensor cores)
    {
        dim3 grid(2, (n + 127) / 128);
        gemm_f16_kernel<<<grid, 256>>>(xh, LDXH, w1t, LDXH, h1, n, 2*HID, K);
    }

    // 3) layer-1 attention scalars
    alpha_kernel<<<(n + 7) / 8, 256>>>(h1, a_src1, a_dst1, as1, ad1, n, 2);

    // 4) layer-1 edge softmax + aggregation
    edge_max_kernel<<<(etot*2 + 255) / 256, 256>>>(ei, ne, etot, as1, ad1, e1, m1, 2);
    edge_exp_kernel<<<(etot*2 + 255) / 256, 256>>>(ei, ne, etot, e1, m1, den1, 2);
    edge_scatter_kernel<<<(etot + 7) / 8, 256>>>(ei, ne, etot, e1, den1, h1, out1, 2);

    // 5) x2h = fp16(relu(out1 + b1))
    bias_relu_h_kernel<<<(n * 256 + 255) / 256, 256>>>(out1, b1, x2h, (size_t)n * 256, 255);

    // 6) GEMM2: h2 = x2h @ W2 (fp16)
    {
        dim3 grid(1, (n + 127) / 128);
        gemm_f16_kernel<<<grid, 256>>>(x2h, 256, w2t, 256, h2, n, HID, 2*HID);
    }

    // 7) layer-2 attention scalars
    alpha_kernel<<<(n + 7) / 8, 256>>>(h2, a_src2, a_dst2, as2, ad2, n, 1);

    // 8) layer-2 edge softmax + aggregation
    edge_max_kernel<<<(etot + 255) / 256, 256>>>(ei, ne, etot, as2, ad2, e2, m2, 1);
    edge_exp_kernel<<<(etot + 255) / 256, 256>>>(ei, ne, etot, e2, m2, den2, 1);
    edge_scatter_kernel<<<(etot + 7) / 8, 256>>>(ei, ne, etot, e2, den2, h2, out2, 1);

    // 9) pooling: mean over graphs of relu(out2 + b2)
    pool_kernel<<<(n + 7) / 8, 256>>>(out2, b2, batch, pool, cnt, n);

    // 10) classifier head
    classifier_kernel<<<NG, 64>>>(pool, cnt, Wc1, bc1, Wc2, bc2, out);
}